// round 3
// baseline (speedup 1.0000x reference)
#include <cuda_runtime.h>
#include <cuda_bf16.h>
#include <cstdint>

// RoPE2D encoder: output = [cos_2d (HW x 128) ; sin_2d (HW x 128)], fp32.
// H = W = 512, DIM = 128. Channels [0,64) depend only on x, [64,128) only on y.
// kernel 1: tiny sincos tables (512 KB) via sincosf.
// kernel 2: 8x8 (x,y) tile per warp -> 8 table LDGs feed 64 row stores.

#define RP_H 512
#define RP_W 512
#define RP_HW (RP_H * RP_W)
#define TILE 8   // tile side (x and y); 8 | 512

// [which(cos=0,sin=1)][pos][channel 0..63]  (channel d uses k = d % 32, duplicated)
__device__ float g_tabx[2][RP_W][64];
__device__ float g_taby[2][RP_H][64];

__global__ void rope2d_build_tables(const float* __restrict__ inv_freq_x,
                                    const float* __restrict__ inv_freq_y) {
    int i = blockIdx.x * blockDim.x + threadIdx.x;   // 0 .. 32767
    if (i >= 2 * 512 * 32) return;
    int table = i >> 14;          // 0 = x-table, 1 = y-table
    int r     = i & 16383;
    int pos   = r >> 5;           // 0..511
    int k     = r & 31;           // 0..31

    float inv = table ? inv_freq_y[k] : inv_freq_x[k];
    float ang = (float)pos * inv;
    float s, c;
    sincosf(ang, &s, &c);

    if (table == 0) {
        g_tabx[0][pos][k]      = c;
        g_tabx[0][pos][k + 32] = c;
        g_tabx[1][pos][k]      = s;
        g_tabx[1][pos][k + 32] = s;
    } else {
        g_taby[0][pos][k]      = c;
        g_taby[0][pos][k + 32] = c;
        g_taby[1][pos][k]      = s;
        g_taby[1][pos][k + 32] = s;
    }
}

// Warp = fixed `which` + 8x8 tile of (x,y) positions = 64 output rows.
// Lane q<16 stores the x-half of each row (float4 chunk q), lane q>=16 the
// y-half (chunk q-16). One LDG per tile index k loads BOTH halves:
//   x-lanes read tabx[x0+k][q], y-lanes read taby[y0+k][q-16].
// Then 64 unrolled SEL+STG.128: row (j,i) takes v[i] on x-lanes, v[j] on y-lanes.
__global__ void __launch_bounds__(256) rope2d_write(float4* __restrict__ out) {
    unsigned warp_in_block = threadIdx.x >> 5;
    unsigned q             = threadIdx.x & 31u;
    unsigned gw    = blockIdx.x * 8u + warp_in_block;   // 0..8191
    unsigned which = gw >> 12;                          // 0 = cos, 1 = sin
    unsigned tile  = gw & 4095u;                        // 0..4095 (64x64 tiles)
    unsigned ty_   = tile >> 6;                         // tile row 0..63
    unsigned tx_   = tile & 63u;                        // tile col 0..63
    unsigned y0    = ty_ * TILE;
    unsigned x0    = tx_ * TILE;

    bool is_x = (q < 16u);
    unsigned qq = q & 15u;

    const float4* tx = reinterpret_cast<const float4*>(g_tabx[which]); // [512][16]
    const float4* ty = reinterpret_cast<const float4*>(g_taby[which]); // [512][16]

    // 8 independent full-warp loads: lane-dependent source table.
    float4 v[TILE];
    #pragma unroll
    for (int k = 0; k < TILE; k++) {
        const float4* src = is_x ? (tx + (x0 + k) * 16u + qq)
                                 : (ty + (y0 + k) * 16u + qq);
        v[k] = *src;
    }

    // Base for row (y0, x0), this lane's chunk.
    float4* base = out + (size_t)which * (RP_HW * 32u)
                       + ((size_t)y0 * 512u + x0) * 32u + q;

    #pragma unroll
    for (int j = 0; j < TILE; j++) {
        float4* row = base + (size_t)j * (512u * 32u);
        #pragma unroll
        for (int i = 0; i < TILE; i++) {
            float4 val = is_x ? v[i] : v[j];
            __stcs(row + (size_t)i * 32u, val);   // streaming store
        }
    }
}

extern "C" void kernel_launch(void* const* d_in, const int* in_sizes, int n_in,
                              void* d_out, int out_size) {
    const float* inv_freq_x = (const float*)d_in[1];
    const float* inv_freq_y = (const float*)d_in[2];
    float4* out = (float4*)d_out;

    // Build tables: 2 * 512 * 32 = 32768 threads
    rope2d_build_tables<<<128, 256>>>(inv_freq_x, inv_freq_y);

    // 8192 warps = 2 (which) x 64 x 64 tiles; 8 warps/block -> 1024 blocks
    rope2d_write<<<1024, 256>>>(out);
}